// round 4
// baseline (speedup 1.0000x reference)
#include <cuda_runtime.h>
#include <stdint.h>

#define DATA_DIM 4096
#define PAIRS    (DATA_DIM / 2)   // 2048
#define QUADS    (DATA_DIM / 4)   // 1024 float4 per row
#define BATCH    16384
#define NBLK     1024             // persistent CTAs, 16 rows each, one wave
#define TPB      256

// Scratch: pair-level permutation map (no device allocation allowed).
__device__ int g_pairmap[PAIRS];

// Build pairmap[j] = perm_idx[2*j] / 2, auto-detecting int32 vs int64 dtype.
// perm_idx[2j+1] is always odd (nonzero): int32 payload -> word[1] != 0;
// little-endian int64 -> word[1] is the high word of perm_idx[0] == 0.
__global__ void build_pairmap_kernel(const void* __restrict__ perm) {
    const int* p32 = (const int*)perm;
    bool is64 = (p32[1] == 0) && (p32[3] == 0) && (p32[5] == 0) && (p32[7] == 0);
    int j = blockIdx.x * blockDim.x + threadIdx.x;
    if (j < PAIRS) {
        int v;
        if (is64) {
            v = (int)((const long long*)perm)[2 * j];
        } else {
            v = p32[2 * j];
        }
        g_pairmap[j] = v >> 1;   // source pair index
    }
}

__device__ __forceinline__ void cp_async16(uint32_t smem_dst, const void* gmem_src) {
    asm volatile("cp.async.cg.shared.global [%0], [%1], 16;\n"
                 :: "r"(smem_dst), "l"(gmem_src));
}
__device__ __forceinline__ void cp_commit() {
    asm volatile("cp.async.commit_group;\n");
}
__device__ __forceinline__ void cp_wait1() {
    asm volatile("cp.async.wait_group 1;\n" ::: "memory");
}
__device__ __forceinline__ void cp_wait0() {
    asm volatile("cp.async.wait_group 0;\n" ::: "memory");
}

// Persistent CTAs, double-buffered cp.async row pipeline.
// Row arrives verbatim (interleaved) in smem: float2 index sp == pair sp.
// Gather = 2x LDS.64, store = coalesced STG.128. DRAM reads never pause.
__global__ void __launch_bounds__(TPB)
permute_pipe_kernel(const float* __restrict__ z, float4* __restrict__ out) {
    __shared__ float2 buf[2][PAIRS];   // 2 x 16KB

    const int tid = threadIdx.x;
    uint32_t sbase[2];
    sbase[0] = (uint32_t)__cvta_generic_to_shared(&buf[0][0]);
    sbase[1] = (uint32_t)__cvta_generic_to_shared(&buf[1][0]);

    const int2* __restrict__ pm = (const int2*)g_pairmap;

    int row = blockIdx.x;

    // Prologue: start streaming first row into buffer 0.
    {
        const float4* src = (const float4*)(z + (long long)row * DATA_DIM);
        #pragma unroll
        for (int i = tid; i < QUADS; i += TPB)
            cp_async16(sbase[0] + i * 16u, src + i);
        cp_commit();
    }

    int s = 0;
    while (row < BATCH) {
        int nrow = row + NBLK;
        if (nrow < BATCH) {
            // Issue next row into the other buffer (free since the barrier at
            // the end of the previous iteration).
            const float4* src = (const float4*)(z + (long long)nrow * DATA_DIM);
            #pragma unroll
            for (int i = tid; i < QUADS; i += TPB)
                cp_async16(sbase[s ^ 1] + i * 16u, src + i);
            cp_commit();
            cp_wait1();   // current row's group has landed
        } else {
            cp_wait0();
        }
        __syncthreads();

        // Gather current row from smem, coalesced quad stores.
        const float2* __restrict__ b = buf[s];
        float4* __restrict__ outr = out + (long long)row * QUADS;
        #pragma unroll
        for (int i = tid; i < QUADS; i += TPB) {
            int2 p = __ldg(&pm[i]);
            float2 a = b[p.x];
            float2 c = b[p.y];
            outr[i] = make_float4(a.x, a.y, c.x, c.y);
        }
        __syncthreads();   // all reads of buf[s] done before it is reused

        row = nrow;
        s ^= 1;
    }
}

extern "C" void kernel_launch(void* const* d_in, const int* in_sizes, int n_in,
                              void* d_out, int out_size) {
    const float* z    = (const float*)d_in[0];
    const void*  perm = d_in[1];
    float4*      out  = (float4*)d_out;

    build_pairmap_kernel<<<(PAIRS + 255) / 256, 256>>>(perm);
    permute_pipe_kernel<<<NBLK, TPB>>>(z, out);
}

// round 5
// speedup vs baseline: 1.2127x; 1.2127x over previous
#include <cuda_runtime.h>
#include <stdint.h>

#define DATA_DIM 4096
#define PAIRS    (DATA_DIM / 2)   // 2048
#define QUADS    (DATA_DIM / 4)   // 1024 float4 per row
#define BATCH    16384
#define NBLK     (148 * 6)        // persistent CTAs, 6/SM
#define TPB      256

// Scratch (no device allocation allowed).
__device__ int g_pairmap[PAIRS];
__device__ int g_row_ctr;

// Build pairmap[j] = perm_idx[2*j] / 2, auto-detecting int32 vs int64 dtype.
// perm_idx[2j+1] is always odd (nonzero): int32 payload -> word[1] != 0;
// little-endian int64 -> word[1] is the high word of perm_idx[0] == 0.
// Also resets the work-stealing counter (same stream => ordered before main).
__global__ void build_pairmap_kernel(const void* __restrict__ perm) {
    if (blockIdx.x == 0 && threadIdx.x == 0) g_row_ctr = NBLK;
    const int* p32 = (const int*)perm;
    bool is64 = (p32[1] == 0) && (p32[3] == 0) && (p32[5] == 0) && (p32[7] == 0);
    int j = blockIdx.x * blockDim.x + threadIdx.x;
    if (j < PAIRS) {
        int v;
        if (is64) {
            v = (int)((const long long*)perm)[2 * j];
        } else {
            v = p32[2 * j];
        }
        g_pairmap[j] = v >> 1;   // source pair index
    }
}

__device__ __forceinline__ void cp_async16(uint32_t smem_dst, const void* gmem_src) {
    asm volatile("cp.async.cg.shared.global [%0], [%1], 16;\n"
                 :: "r"(smem_dst), "l"(gmem_src));
}
__device__ __forceinline__ void cp_commit() {
    asm volatile("cp.async.commit_group;\n");
}
__device__ __forceinline__ void cp_wait1() {
    asm volatile("cp.async.wait_group 1;\n" ::: "memory");
}
__device__ __forceinline__ void cp_wait0() {
    asm volatile("cp.async.wait_group 0;\n" ::: "memory");
}

// Persistent CTAs + double-buffered cp.async pipeline + atomic work stealing.
// Row arrives verbatim in smem (float2 index sp == pair sp). Gather = 2x
// LDS.64, store = coalesced STG.128. Work stealing collapses multi-CTA spread.
__global__ void __launch_bounds__(TPB)
permute_ws_kernel(const float* __restrict__ z, float4* __restrict__ out) {
    __shared__ float2 buf[2][PAIRS];   // 2 x 16KB
    __shared__ int s_next;

    const int tid = threadIdx.x;
    uint32_t sbase[2];
    sbase[0] = (uint32_t)__cvta_generic_to_shared(&buf[0][0]);
    sbase[1] = (uint32_t)__cvta_generic_to_shared(&buf[1][0]);

    const int2* __restrict__ pm = (const int2*)g_pairmap;

    int r_land = blockIdx.x;   // first row, statically assigned (< BATCH)

    // Prologue: stream first row into buffer 0, grab the next row.
    {
        const float4* src = (const float4*)(z + (long long)r_land * DATA_DIM);
        #pragma unroll
        for (int i = tid; i < QUADS; i += TPB)
            cp_async16(sbase[0] + i * 16u, src + i);
        cp_commit();
    }
    if (tid == 0) s_next = atomicAdd(&g_row_ctr, 1);
    __syncthreads();   // broadcast s_next

    int s = 0;
    while (true) {
        const int r_pf = s_next;   // row to prefetch (all threads agree)
        if (r_pf < BATCH) {
            const float4* src = (const float4*)(z + (long long)r_pf * DATA_DIM);
            #pragma unroll
            for (int i = tid; i < QUADS; i += TPB)
                cp_async16(sbase[s ^ 1] + i * 16u, src + i);
            cp_commit();
            cp_wait1();   // current row (buf[s]) has landed
        } else {
            cp_wait0();
        }
        __syncthreads();   // (A) buf[s] visible to all; s_next reads done

        // Grab the row after next; overlaps with the gather below.
        if (tid == 0 && r_pf < BATCH) s_next = atomicAdd(&g_row_ctr, 1);

        // Gather current row from smem, coalesced quad stores.
        const float2* __restrict__ b = buf[s];
        float4* __restrict__ outr = out + (long long)r_land * QUADS;
        #pragma unroll
        for (int i = tid; i < QUADS; i += TPB) {
            int2 p = __ldg(&pm[i]);
            float2 a = b[p.x];
            float2 c = b[p.y];
            outr[i] = make_float4(a.x, a.y, c.x, c.y);
        }

        if (r_pf >= BATCH) break;   // the row just gathered was our last
        r_land = r_pf;
        s ^= 1;
        __syncthreads();   // (B) gather reads of old buffer done; s_next broadcast
    }
}

extern "C" void kernel_launch(void* const* d_in, const int* in_sizes, int n_in,
                              void* d_out, int out_size) {
    const float* z    = (const float*)d_in[0];
    const void*  perm = d_in[1];
    float4*      out  = (float4*)d_out;

    build_pairmap_kernel<<<(PAIRS + 255) / 256, 256>>>(perm);
    permute_ws_kernel<<<NBLK, TPB>>>(z, out);
}

// round 6
// speedup vs baseline: 1.2210x; 1.0068x over previous
#include <cuda_runtime.h>
#include <stdint.h>

#define DATA_DIM 4096
#define PAIRS    (DATA_DIM / 2)   // 2048
#define QUADS    (DATA_DIM / 4)   // 1024 float4 per row
#define BATCH    16384
#define NBLK     (148 * 6)        // persistent CTAs, 6/SM
#define TPB      256
#define MODM     ((unsigned long long)(BATCH + NBLK))

// Work-stealing counter. Zero at module load; every kernel execution performs
// exactly BATCH real grabs + NBLK null grabs (one terminator per CTA), so the
// counter advances by exactly MODM per launch and row = v % MODM stays valid
// across graph replays with no reset and no static guards.
__device__ unsigned long long g_ctr;

__device__ __forceinline__ void cp_async16(uint32_t smem_dst, const void* gmem_src) {
    asm volatile("cp.async.cg.shared.global [%0], [%1], 16;\n"
                 :: "r"(smem_dst), "l"(gmem_src));
}
__device__ __forceinline__ void cp_commit() {
    asm volatile("cp.async.commit_group;\n");
}
__device__ __forceinline__ void cp_wait1() {
    asm volatile("cp.async.wait_group 1;\n" ::: "memory");
}
__device__ __forceinline__ void cp_wait0() {
    asm volatile("cp.async.wait_group 0;\n" ::: "memory");
}

// Single fused kernel: persistent CTAs, double-buffered cp.async row pipeline,
// modular atomic work stealing, pair-map held in registers (loaded once from
// perm_idx, int32/int64 auto-detected). Row lands verbatim in smem so float2
// index sp == source pair sp; gather = 2x LDS.64, store = coalesced STG.128.
__global__ void __launch_bounds__(TPB)
permute_fused_kernel(const float* __restrict__ z, const void* __restrict__ perm,
                     float4* __restrict__ out) {
    __shared__ float2 buf[2][PAIRS];   // 2 x 16KB
    __shared__ int s_next;

    const int tid = threadIdx.x;

    // ---- Pair-map -> registers. Quad i needs source pairs perm[4i]>>1 and
    // perm[4i+2]>>1 (even entries; odd entries are them +1 by construction).
    // dtype detect: perm[1] is always odd => int32 word[1] != 0; int64 high
    // word of perm[0] == 0.
    const int* p32 = (const int*)perm;
    const bool is64 = (p32[1] == 0) && (p32[3] == 0) && (p32[5] == 0) && (p32[7] == 0);
    int2 pq[4];
    #pragma unroll
    for (int k = 0; k < 4; k++) {
        int i = tid + k * TPB;
        int e0, e1;
        if (is64) {
            e0 = (int)((const long long*)perm)[4 * i];
            e1 = (int)((const long long*)perm)[4 * i + 2];
        } else {
            e0 = p32[4 * i];
            e1 = p32[4 * i + 2];
        }
        pq[k] = make_int2(e0 >> 1, e1 >> 1);
    }

    uint32_t sbase[2];
    sbase[0] = (uint32_t)__cvta_generic_to_shared(&buf[0][0]);
    sbase[1] = (uint32_t)__cvta_generic_to_shared(&buf[1][0]);

    // ---- First row via counter.
    if (tid == 0) s_next = (int)(atomicAdd(&g_ctr, 1ULL) % MODM);
    __syncthreads();
    int r_land = s_next;
    if (r_land >= BATCH) return;   // got terminator immediately (rare)

    {   // Prologue: stream first row into buffer 0, grab the next row.
        const float4* src = (const float4*)(z + (long long)r_land * DATA_DIM);
        #pragma unroll
        for (int k = 0; k < 4; k++)
            cp_async16(sbase[0] + (tid + k * TPB) * 16u, src + tid + k * TPB);
        cp_commit();
    }
    if (tid == 0) s_next = (int)(atomicAdd(&g_ctr, 1ULL) % MODM);
    __syncthreads();   // broadcast s_next

    int s = 0;
    while (true) {
        const int r_pf = s_next;   // row to prefetch (all threads agree)
        if (r_pf < BATCH) {
            const float4* src = (const float4*)(z + (long long)r_pf * DATA_DIM);
            #pragma unroll
            for (int k = 0; k < 4; k++)
                cp_async16(sbase[s ^ 1] + (tid + k * TPB) * 16u, src + tid + k * TPB);
            cp_commit();
            cp_wait1();   // current row (buf[s]) has landed
        } else {
            cp_wait0();
        }
        __syncthreads();   // (A) buf[s] visible to all; s_next reads done

        // Grab the row after next; latency overlaps the gather below.
        if (tid == 0 && r_pf < BATCH)
            s_next = (int)(atomicAdd(&g_ctr, 1ULL) % MODM);

        // Gather current row from smem, coalesced quad stores.
        const float2* __restrict__ b = buf[s];
        float4* __restrict__ outr = out + (long long)r_land * QUADS;
        #pragma unroll
        for (int k = 0; k < 4; k++) {
            int2 p = pq[k];
            float2 a = b[p.x];
            float2 c = b[p.y];
            outr[tid + k * TPB] = make_float4(a.x, a.y, c.x, c.y);
        }

        if (r_pf >= BATCH) break;   // the row just gathered was our last
        r_land = r_pf;
        s ^= 1;
        __syncthreads();   // (B) gather reads of old buffer done; s_next broadcast
    }
}

extern "C" void kernel_launch(void* const* d_in, const int* in_sizes, int n_in,
                              void* d_out, int out_size) {
    const float* z    = (const float*)d_in[0];
    const void*  perm = d_in[1];
    float4*      out  = (float4*)d_out;

    permute_fused_kernel<<<NBLK, TPB>>>(z, perm, out);
}

// round 7
// speedup vs baseline: 1.2223x; 1.0011x over previous
#include <cuda_runtime.h>
#include <stdint.h>

#define DATA_DIM  4096
#define PAIRS     (DATA_DIM / 2)     // 2048
#define QUADS     (DATA_DIM / 4)     // 1024 float4 per row
#define ROW_BYTES (DATA_DIM * 4)     // 16384
#define BATCH     16384
#define NBLK      (148 * 3)          // persistent CTAs, 3/SM (64KB smem each)
#define TPB       256
#define MODM      ((unsigned long long)(BATCH + NBLK))

// Dynamic smem layout
#define SM_IN0   0
#define SM_IN1   16384
#define SM_OUT0  32768
#define SM_OUT1  49152
#define SM_MBAR  65536               // two 8-byte mbarriers
#define SMEM_SZ  (65536 + 64)

// Work-stealing counter. Zero at module load; each launch consumes exactly
// BATCH real grabs + NBLK terminator grabs (each CTA stops at its first
// terminator), so the counter advances by exactly MODM per launch and
// row = v % MODM stays valid across graph replays with no reset.
__device__ unsigned long long g_ctr;

__device__ __forceinline__ int grab_row() {
    return (int)(atomicAdd(&g_ctr, 1ULL) % MODM);
}

__device__ __forceinline__ void mbar_init(uint32_t mbar, uint32_t cnt) {
    asm volatile("mbarrier.init.shared.b64 [%0], %1;" :: "r"(mbar), "r"(cnt) : "memory");
}
__device__ __forceinline__ void mbar_expect_tx(uint32_t mbar, uint32_t bytes) {
    asm volatile("mbarrier.arrive.expect_tx.shared.b64 _, [%0], %1;"
                 :: "r"(mbar), "r"(bytes) : "memory");
}
__device__ __forceinline__ void mbar_wait(uint32_t mbar, uint32_t parity) {
    uint32_t done;
    asm volatile(
        "{\n\t.reg .pred p;\n\t"
        "mbarrier.try_wait.parity.acquire.cta.shared::cta.b64 p, [%1], %2;\n\t"
        "selp.b32 %0, 1, 0, p;\n\t}"
        : "=r"(done) : "r"(mbar), "r"(parity) : "memory");
    if (!done) {
        asm volatile(
            "{\n\t.reg .pred P1;\n\t"
            "W_%=:\n\t"
            "mbarrier.try_wait.parity.acquire.cta.shared::cta.b64 P1, [%0], %1, 0x989680;\n\t"
            "@P1 bra.uni D_%=;\n\t"
            "bra.uni W_%=;\n\t"
            "D_%=:\n\t}"
            :: "r"(mbar), "r"(parity) : "memory");
    }
}
__device__ __forceinline__ void bulk_load_row(uint32_t sdst, const void* gsrc, uint32_t mbar) {
    asm volatile(
        "cp.async.bulk.shared::cta.global.mbarrier::complete_tx::bytes [%0], [%1], %2, [%3];"
        :: "r"(sdst), "l"(gsrc), "r"((uint32_t)ROW_BYTES), "r"(mbar) : "memory");
}
__device__ __forceinline__ void bulk_store_row(void* gdst, uint32_t ssrc) {
    asm volatile("cp.async.bulk.global.shared::cta.bulk_group [%0], [%1], %2;"
                 :: "l"(gdst), "r"(ssrc), "r"((uint32_t)ROW_BYTES) : "memory");
    asm volatile("cp.async.bulk.commit_group;" ::: "memory");
}
__device__ __forceinline__ void bulk_store_wait1() {
    asm volatile("cp.async.bulk.wait_group.read 1;" ::: "memory");
}
__device__ __forceinline__ void bulk_store_wait0() {
    asm volatile("cp.async.bulk.wait_group 0;" ::: "memory");
}
__device__ __forceinline__ void fence_async() {
    asm volatile("fence.proxy.async.shared::cta;" ::: "memory");
}

// Persistent CTAs. Per row: one TMA bulk load in, CTA-wide smem gather
// (2x LDS.64 -> STS.128, conflict-free stores), one TMA bulk store out.
// Double-buffered input AND output staging; atomic work stealing.
__global__ void __launch_bounds__(TPB)
permute_tma_kernel(const float* __restrict__ z, const void* __restrict__ perm,
                   float* __restrict__ out) {
    extern __shared__ char smem[];
    __shared__ int s_next;

    const int tid = threadIdx.x;
    const uint32_t sbase = (uint32_t)__cvta_generic_to_shared(smem);
    const uint32_t mbar[2] = { sbase + SM_MBAR, sbase + SM_MBAR + 8 };
    float2* const inb[2]  = { (float2*)(smem + SM_IN0),  (float2*)(smem + SM_IN1) };
    float4* const outb[2] = { (float4*)(smem + SM_OUT0), (float4*)(smem + SM_OUT1) };

    // ---- Pair-map -> registers. Quad i needs source pairs perm[4i]>>1 and
    // perm[4i+2]>>1. dtype detect: perm[1] is always odd => int32 word[1]!=0;
    // little-endian int64 high word of perm[0] == 0.
    const int* p32 = (const int*)perm;
    const bool is64 = (p32[1] == 0) && (p32[3] == 0) && (p32[5] == 0) && (p32[7] == 0);
    int2 pq[4];
    #pragma unroll
    for (int k = 0; k < 4; k++) {
        int i = tid + k * TPB;
        int e0, e1;
        if (is64) {
            e0 = (int)((const long long*)perm)[4 * i];
            e1 = (int)((const long long*)perm)[4 * i + 2];
        } else {
            e0 = p32[4 * i];
            e1 = p32[4 * i + 2];
        }
        pq[k] = make_int2(e0 >> 1, e1 >> 1);
    }

    if (tid == 0) {
        mbar_init(mbar[0], 1);
        mbar_init(mbar[1], 1);
        s_next = grab_row();
    }
    __syncthreads();

    int r_cur = s_next;
    if (r_cur >= BATCH) return;   // immediate terminator (rare)

    // Prologue: start load of first row into in[0]; grab following row.
    if (tid == 0) {
        mbar_expect_tx(mbar[0], ROW_BYTES);
        bulk_load_row(sbase + SM_IN0, z + (long long)r_cur * DATA_DIM, mbar[0]);
        s_next = grab_row();
    }
    __syncthreads();
    int r_next = s_next;

    int s = 0;
    uint32_t ph0 = 0, ph1 = 0;

    while (true) {
        // Prefetch next row into in[s^1]; free outbuf[s]; grab row after next.
        if (tid == 0) {
            if (r_next < BATCH) {
                mbar_expect_tx(mbar[s ^ 1], ROW_BYTES);
                bulk_load_row(sbase + (s ? SM_IN0 : SM_IN1),
                              z + (long long)r_next * DATA_DIM, mbar[s ^ 1]);
                s_next = grab_row();
            }
            bulk_store_wait1();   // store issued 2 rows ago (outbuf[s]) is done
        }
        __syncthreads();          // outbuf[s] free + s_next visible to all
        const int r_next2 = s_next;

        // Wait for current row's TMA load.
        if (s == 0) { mbar_wait(mbar[0], ph0); ph0 ^= 1; }
        else        { mbar_wait(mbar[1], ph1); ph1 ^= 1; }

        // Gather in[s] -> outbuf[s] (random LDS.64 x2, conflict-free STS.128).
        {
            const float2* __restrict__ b = inb[s];
            float4* __restrict__ o = outb[s];
            #pragma unroll
            for (int k = 0; k < 4; k++) {
                int2 p = pq[k];
                float2 a = b[p.x];
                float2 c = b[p.y];
                o[tid + k * TPB] = make_float4(a.x, a.y, c.x, c.y);
            }
        }
        __syncthreads();          // all STS done; all reads of in[s] done

        // Issue async bulk store of the gathered row.
        if (tid == 0) {
            fence_async();
            bulk_store_row(out + (long long)r_cur * DATA_DIM, sbase + (s ? SM_OUT1 : SM_OUT0));
        }

        if (r_next >= BATCH) break;
        r_cur = r_next;
        r_next = r_next2;
        s ^= 1;
    }

    // Drain outstanding stores before exit.
    if (tid == 0) bulk_store_wait0();
}

extern "C" void kernel_launch(void* const* d_in, const int* in_sizes, int n_in,
                              void* d_out, int out_size) {
    const float* z    = (const float*)d_in[0];
    const void*  perm = d_in[1];
    float*       out  = (float*)d_out;

    cudaFuncSetAttribute(permute_tma_kernel,
                         cudaFuncAttributeMaxDynamicSharedMemorySize, SMEM_SZ);
    permute_tma_kernel<<<NBLK, TPB, SMEM_SZ>>>(z, perm, out);
}

// round 8
// speedup vs baseline: 1.2369x; 1.0119x over previous
#include <cuda_runtime.h>
#include <stdint.h>

#define DATA_DIM  4096
#define PAIRS     (DATA_DIM / 2)     // 2048
#define QUADS     (DATA_DIM / 4)     // 1024 float4 per row
#define ROW_BYTES (DATA_DIM * 4)     // 16384
#define BATCH     16384
#define NBLK      (148 * 2)          // persistent CTAs, 2/SM (80KB smem each)
#define TPB       256
#define MODM      ((unsigned long long)(BATCH + NBLK))
#define DEPTH     3                  // input pipeline stages
#define OUTS      2                  // output staging buffers
#define ROW_END   0x7fffffff

// Dynamic smem layout: 3 in + 2 out + mbarriers
#define SM_IN(i)   ((i) * 16384)
#define SM_OUT(i)  (49152 + (i) * 16384)
#define SM_MBAR    81920
#define SMEM_SZ    (81920 + 64)

// Work-stealing counter. Zero at module load; each launch consumes exactly
// BATCH real grabs + NBLK terminator grabs (each CTA stops grabbing at its
// first terminator), so the counter advances by exactly MODM per launch and
// row = v % MODM stays valid across graph replays with no reset.
__device__ unsigned long long g_ctr;

__device__ __forceinline__ void mbar_init(uint32_t mbar, uint32_t cnt) {
    asm volatile("mbarrier.init.shared.b64 [%0], %1;" :: "r"(mbar), "r"(cnt) : "memory");
}
__device__ __forceinline__ void mbar_expect_tx(uint32_t mbar, uint32_t bytes) {
    asm volatile("mbarrier.arrive.expect_tx.shared.b64 _, [%0], %1;"
                 :: "r"(mbar), "r"(bytes) : "memory");
}
__device__ __forceinline__ void mbar_wait(uint32_t mbar, uint32_t parity) {
    uint32_t done;
    asm volatile(
        "{\n\t.reg .pred p;\n\t"
        "mbarrier.try_wait.parity.acquire.cta.shared::cta.b64 p, [%1], %2;\n\t"
        "selp.b32 %0, 1, 0, p;\n\t}"
        : "=r"(done) : "r"(mbar), "r"(parity) : "memory");
    if (!done) {
        asm volatile(
            "{\n\t.reg .pred P1;\n\t"
            "W_%=:\n\t"
            "mbarrier.try_wait.parity.acquire.cta.shared::cta.b64 P1, [%0], %1, 0x989680;\n\t"
            "@P1 bra.uni D_%=;\n\t"
            "bra.uni W_%=;\n\t"
            "D_%=:\n\t}"
            :: "r"(mbar), "r"(parity) : "memory");
    }
}
__device__ __forceinline__ void bulk_load_row(uint32_t sdst, const void* gsrc, uint32_t mbar) {
    asm volatile(
        "cp.async.bulk.shared::cta.global.mbarrier::complete_tx::bytes [%0], [%1], %2, [%3];"
        :: "r"(sdst), "l"(gsrc), "r"((uint32_t)ROW_BYTES), "r"(mbar) : "memory");
}
__device__ __forceinline__ void bulk_store_row(void* gdst, uint32_t ssrc) {
    asm volatile("cp.async.bulk.global.shared::cta.bulk_group [%0], [%1], %2;"
                 :: "l"(gdst), "r"(ssrc), "r"((uint32_t)ROW_BYTES) : "memory");
    asm volatile("cp.async.bulk.commit_group;" ::: "memory");
}
// Wait until at most 1 store group has NOT finished READING its smem source.
__device__ __forceinline__ void bulk_store_wait_read1() {
    asm volatile("cp.async.bulk.wait_group.read 1;" ::: "memory");
}
__device__ __forceinline__ void bulk_store_wait0() {
    asm volatile("cp.async.bulk.wait_group 0;" ::: "memory");
}
__device__ __forceinline__ void fence_async() {
    asm volatile("fence.proxy.async.shared::cta;" ::: "memory");
}

// Persistent CTAs, 3-deep TMA input ring + 2 output staging buffers.
// Per row: one bulk load in, CTA-wide smem gather (2x LDS.64 -> STS.128),
// one bulk store out. Atomic work stealing keeps CTAs balanced; depth-3
// keeps >=2 loads in flight per CTA at every point of the loop.
__global__ void __launch_bounds__(TPB)
permute_tma3_kernel(const float* __restrict__ z, const void* __restrict__ perm,
                    float* __restrict__ out) {
    extern __shared__ char smem[];
    __shared__ int s_row[DEPTH];   // row assigned to each pipeline slot

    const int tid = threadIdx.x;
    const uint32_t sbase = (uint32_t)__cvta_generic_to_shared(smem);

    // ---- Pair-map -> registers. Quad i needs source pairs perm[4i]>>1 and
    // perm[4i+2]>>1. dtype detect: perm[1] is always odd => int32 word[1]!=0;
    // little-endian int64 high word of perm[0] == 0.
    const int* p32 = (const int*)perm;
    const bool is64 = (p32[1] == 0) && (p32[3] == 0) && (p32[5] == 0) && (p32[7] == 0);
    int2 pq[4];
    #pragma unroll
    for (int k = 0; k < 4; k++) {
        int i = tid + k * TPB;
        int e0, e1;
        if (is64) {
            e0 = (int)((const long long*)perm)[4 * i];
            e1 = (int)((const long long*)perm)[4 * i + 2];
        } else {
            e0 = p32[4 * i];
            e1 = p32[4 * i + 2];
        }
        pq[k] = make_int2(e0 >> 1, e1 >> 1);
    }

    // ---- Prologue: init mbarriers, grab + issue up to DEPTH row loads.
    bool stop = false;   // meaningful in tid0 only
    if (tid == 0) {
        #pragma unroll
        for (int d = 0; d < DEPTH; d++) mbar_init(sbase + SM_MBAR + 8 * d, 1);
        fence_async();
        #pragma unroll
        for (int d = 0; d < DEPTH; d++) {
            int r = ROW_END;
            if (!stop) {
                int v = (int)(atomicAdd(&g_ctr, 1ULL) % MODM);
                if (v < BATCH) r = v; else stop = true;
            }
            s_row[d] = r;
            if (r != ROW_END) {
                mbar_expect_tx(sbase + SM_MBAR + 8 * d, ROW_BYTES);
                bulk_load_row(sbase + SM_IN(d), z + (long long)r * DATA_DIM,
                              sbase + SM_MBAR + 8 * d);
            }
        }
    }
    __syncthreads();

    uint32_t ph[DEPTH] = {0, 0, 0};
    int it = 0;

    while (true) {
        const int slot  = it % DEPTH;
        const int oslot = it & (OUTS - 1);
        const int r_cur = s_row[slot];
        if (r_cur == ROW_END) break;

        // Free out[oslot]: the store issued 2 iterations ago must have
        // finished reading smem (not the DRAM write).
        if (tid == 0) bulk_store_wait_read1();

        // Wait for this slot's TMA load.
        mbar_wait(sbase + SM_MBAR + 8 * slot, ph[slot]);
        ph[slot] ^= 1;
        __syncthreads();   // out[oslot] free (tid0's wait) visible to all

        // Gather in[slot] -> out[oslot]: random LDS.64 x2, conflict-free STS.128.
        {
            const float2* __restrict__ b = (const float2*)(smem + SM_IN(slot));
            float4* __restrict__ o = (float4*)(smem + SM_OUT(oslot));
            #pragma unroll
            for (int k = 0; k < 4; k++) {
                int2 p = pq[k];
                float2 a = b[p.x];
                float2 c = b[p.y];
                o[tid + k * TPB] = make_float4(a.x, a.y, c.x, c.y);
            }
        }
        __syncthreads();   // gather done: in[slot] reusable, out[oslot] filled

        if (tid == 0) {
            // Issue async store of the gathered row.
            fence_async();
            bulk_store_row(out + (long long)r_cur * DATA_DIM, sbase + SM_OUT(oslot));
            // Refill this pipeline slot with a freshly stolen row.
            int r = ROW_END;
            if (!stop) {
                int v = (int)(atomicAdd(&g_ctr, 1ULL) % MODM);
                if (v < BATCH) r = v; else stop = true;
            }
            s_row[slot] = r;
            if (r != ROW_END) {
                mbar_expect_tx(sbase + SM_MBAR + 8 * slot, ROW_BYTES);
                bulk_load_row(sbase + SM_IN(slot), z + (long long)r * DATA_DIM,
                              sbase + SM_MBAR + 8 * slot);
            }
        }
        it++;
        __syncthreads();   // s_row[slot] update visible before next wraparound
    }

    // Drain outstanding stores before exit.
    if (tid == 0) bulk_store_wait0();
}

extern "C" void kernel_launch(void* const* d_in, const int* in_sizes, int n_in,
                              void* d_out, int out_size) {
    const float* z    = (const float*)d_in[0];
    const void*  perm = d_in[1];
    float*       out  = (float*)d_out;

    cudaFuncSetAttribute(permute_tma3_kernel,
                         cudaFuncAttributeMaxDynamicSharedMemorySize, SMEM_SZ);
    permute_tma3_kernel<<<NBLK, TPB, SMEM_SZ>>>(z, perm, out);
}

// round 9
// speedup vs baseline: 1.2393x; 1.0019x over previous
#include <cuda_runtime.h>
#include <stdint.h>

#define DATA_DIM  4096
#define PAIRS     (DATA_DIM / 2)     // 2048
#define QUADS     (DATA_DIM / 4)     // 1024 float4 per row
#define ROW_BYTES (DATA_DIM * 4)     // 16384
#define BATCH     16384
#define NBLK      (148 * 7)          // persistent CTAs, 7/SM (32KB smem each)
#define TPB       256
#define MODM      ((unsigned long long)(BATCH + NBLK))
#define ROW_END   0x7fffffff

// Dynamic smem: 2 input row buffers + mbarriers.
#define SM_IN(i)   ((i) * 16384)
#define SM_MBAR    32768
#define SMEM_SZ    (32768 + 64)

// Work-stealing counter. Zero at module load; each launch consumes exactly
// BATCH real grabs + NBLK terminator grabs (each CTA stops grabbing at its
// first terminator), so the counter advances by exactly MODM per launch and
// row = v % MODM stays valid across graph replays with no reset.
__device__ unsigned long long g_ctr;

__device__ __forceinline__ void mbar_init(uint32_t mbar, uint32_t cnt) {
    asm volatile("mbarrier.init.shared.b64 [%0], %1;" :: "r"(mbar), "r"(cnt) : "memory");
}
__device__ __forceinline__ void mbar_expect_tx(uint32_t mbar, uint32_t bytes) {
    asm volatile("mbarrier.arrive.expect_tx.shared.b64 _, [%0], %1;"
                 :: "r"(mbar), "r"(bytes) : "memory");
}
__device__ __forceinline__ void mbar_wait(uint32_t mbar, uint32_t parity) {
    uint32_t done;
    asm volatile(
        "{\n\t.reg .pred p;\n\t"
        "mbarrier.try_wait.parity.acquire.cta.shared::cta.b64 p, [%1], %2;\n\t"
        "selp.b32 %0, 1, 0, p;\n\t}"
        : "=r"(done) : "r"(mbar), "r"(parity) : "memory");
    if (!done) {
        asm volatile(
            "{\n\t.reg .pred P1;\n\t"
            "W_%=:\n\t"
            "mbarrier.try_wait.parity.acquire.cta.shared::cta.b64 P1, [%0], %1, 0x989680;\n\t"
            "@P1 bra.uni D_%=;\n\t"
            "bra.uni W_%=;\n\t"
            "D_%=:\n\t}"
            :: "r"(mbar), "r"(parity) : "memory");
    }
}
__device__ __forceinline__ void bulk_load_row(uint32_t sdst, const void* gsrc, uint32_t mbar) {
    asm volatile(
        "cp.async.bulk.shared::cta.global.mbarrier::complete_tx::bytes [%0], [%1], %2, [%3];"
        :: "r"(sdst), "l"(gsrc), "r"((uint32_t)ROW_BYTES), "r"(mbar) : "memory");
}
__device__ __forceinline__ void stg128_cs(float4* p, float4 v) {
    asm volatile("st.global.cs.v4.f32 [%0], {%1, %2, %3, %4};"
                 :: "l"(p), "f"(v.x), "f"(v.y), "f"(v.z), "f"(v.w) : "memory");
}
__device__ __forceinline__ void fence_async() {
    asm volatile("fence.proxy.async.shared::cta;" ::: "memory");
}

// Persistent CTAs, depth-2 TMA input ring, register gather, DIRECT streaming
// STG.128 output (no smem staging pass). 7 CTAs/SM maximizes per-SM rows in
// flight (14); atomic work stealing keeps CTAs balanced to row granularity.
__global__ void __launch_bounds__(TPB)
permute_tma_stg_kernel(const float* __restrict__ z, const void* __restrict__ perm,
                       float* __restrict__ out) {
    extern __shared__ char smem[];
    __shared__ int s_row[2];   // row assigned to each pipeline slot

    const int tid = threadIdx.x;
    const uint32_t sbase = (uint32_t)__cvta_generic_to_shared(smem);

    // ---- Pair-map -> registers. Quad i needs source pairs perm[4i]>>1 and
    // perm[4i+2]>>1. dtype detect: perm[1] is always odd => int32 word[1]!=0;
    // little-endian int64 high word of perm[0] == 0.
    const int* p32 = (const int*)perm;
    const bool is64 = (p32[1] == 0) && (p32[3] == 0) && (p32[5] == 0) && (p32[7] == 0);
    int2 pq[4];
    #pragma unroll
    for (int k = 0; k < 4; k++) {
        int i = tid + k * TPB;
        int e0, e1;
        if (is64) {
            e0 = (int)((const long long*)perm)[4 * i];
            e1 = (int)((const long long*)perm)[4 * i + 2];
        } else {
            e0 = p32[4 * i];
            e1 = p32[4 * i + 2];
        }
        pq[k] = make_int2(e0 >> 1, e1 >> 1);
    }

    // ---- Prologue: init mbarriers, steal + issue up to 2 row loads.
    bool stop = false;   // meaningful in tid0 only
    if (tid == 0) {
        mbar_init(sbase + SM_MBAR, 1);
        mbar_init(sbase + SM_MBAR + 8, 1);
        fence_async();
        #pragma unroll
        for (int d = 0; d < 2; d++) {
            int r = ROW_END;
            if (!stop) {
                int v = (int)(atomicAdd(&g_ctr, 1ULL) % MODM);
                if (v < BATCH) r = v; else stop = true;
            }
            s_row[d] = r;
            if (r != ROW_END) {
                mbar_expect_tx(sbase + SM_MBAR + 8 * d, ROW_BYTES);
                bulk_load_row(sbase + SM_IN(d), z + (long long)r * DATA_DIM,
                              sbase + SM_MBAR + 8 * d);
            }
        }
    }
    __syncthreads();

    uint32_t ph[2] = {0, 0};
    int it = 0;

    while (true) {
        const int slot = it & 1;
        const int r_cur = s_row[slot];
        if (r_cur == ROW_END) break;

        // Wait for this slot's TMA load, then gather straight to gmem.
        mbar_wait(sbase + SM_MBAR + 8 * slot, ph[slot]);
        ph[slot] ^= 1;

        {
            const float2* __restrict__ b = (const float2*)(smem + SM_IN(slot));
            float4* __restrict__ o = (float4*)(out + (long long)r_cur * DATA_DIM);
            #pragma unroll
            for (int k = 0; k < 4; k++) {
                int2 p = pq[k];
                float2 a = b[p.x];
                float2 c = b[p.y];
                stg128_cs(o + tid + k * TPB, make_float4(a.x, a.y, c.x, c.y));
            }
        }
        __syncthreads();   // all reads of in[slot] done before refill

        if (tid == 0) {
            int r = ROW_END;
            if (!stop) {
                int v = (int)(atomicAdd(&g_ctr, 1ULL) % MODM);
                if (v < BATCH) r = v; else stop = true;
            }
            s_row[slot] = r;
            if (r != ROW_END) {
                mbar_expect_tx(sbase + SM_MBAR + 8 * slot, ROW_BYTES);
                bulk_load_row(sbase + SM_IN(slot), z + (long long)r * DATA_DIM,
                              sbase + SM_MBAR + 8 * slot);
            }
        }
        it++;
        __syncthreads();   // s_row[slot] visible before next use of this slot
    }
}

extern "C" void kernel_launch(void* const* d_in, const int* in_sizes, int n_in,
                              void* d_out, int out_size) {
    const float* z    = (const float*)d_in[0];
    const void*  perm = d_in[1];
    float*       out  = (float*)d_out;

    cudaFuncSetAttribute(permute_tma_stg_kernel,
                         cudaFuncAttributeMaxDynamicSharedMemorySize, SMEM_SZ);
    permute_tma_stg_kernel<<<NBLK, TPB, SMEM_SZ>>>(z, perm, out);
}